// round 9
// baseline (speedup 1.0000x reference)
#include <cuda_runtime.h>

#define BB 64
#define TT 512
#define HH 128
#define LL 8
#define OUTD 65
#define GG 512
#define CTAS_PER_LAYER 16
#define LSTM_CTAS (LL * CTAS_PER_LAYER)   // 128
#define PROJ_CTAS 16
#define NCTA (LSTM_CTAS + PROJ_CTAS)      // 144
#define NTHR 256

#define OUTBASE ((long long)BB * TT * OUTD)
#define STATESZ ((long long)LL * BB * HH)
#define TOTALOUT (OUTBASE + 2 * STATESZ)

typedef unsigned long long u64;
typedef unsigned int u32;

// ---------------- device scratch ------------------------------------------
__device__ float g_ring[4][LL][HH][BB];   // 4-deep h ring, k-major
__device__ float g_xe[TT][HH][BB];        // embedded input, k-major
__device__ float g_h7[TT][HH][BB];        // layer-7 h stream
__device__ u32 g_done[LL * 32];           // per-layer counters (64B apart)
__device__ u64 g_bar_ctr = 0;             // one-time grid barrier (monotonic)
__device__ u64 g_bar_rel = 0;

// ---------------- helpers -------------------------------------------------
__device__ __forceinline__ float sigf(float x) { return 1.0f / (1.0f + __expf(-x)); }
__device__ __forceinline__ float tanhf_(float x) { return 2.0f / (1.0f + __expf(-2.0f * x)) - 1.0f; }
__device__ __forceinline__ u64 pack2(float x, float y) {
    u64 r; asm("mov.b64 %0, {%1,%2};" : "=l"(r) : "f"(x), "f"(y)); return r;
}
#define FMA2(d, a, b) \
    asm("fma.rn.f32x2 %0, %1, %2, %0;" : "+l"(d) : "l"(a), "l"(b))

__device__ __forceinline__ u32 ld_acq(const u32* p) {
    u32 v; asm volatile("ld.acquire.gpu.global.u32 %0, [%1];" : "=r"(v) : "l"(p)); return v;
}
__device__ __forceinline__ void red_rel(u32* p) {
    asm volatile("red.release.gpu.global.add.u32 [%0], %1;" :: "l"(p), "r"(1u) : "memory");
}
__device__ __forceinline__ u32 smem_u32(const void* p) {
    return (u32)__cvta_generic_to_shared(p);
}
#define CP16(s, g) asm volatile("cp.async.cg.shared.global [%0], [%1], 16;" :: "r"(s), "l"(g))
#define CP_COMMIT_WAIT() do { \
    asm volatile("cp.async.commit_group;"); \
    asm volatile("cp.async.wait_group 0;" ::: "memory"); } while (0)

// ld.global.cg 16B vector (L2-coherent, compiler may schedule freely)
__device__ __forceinline__ ulonglong2 ldcg2(const ulonglong2* p) {
    ulonglong2 v;
    asm("ld.global.cg.v2.u64 {%0,%1}, [%2];" : "=l"(v.x), "=l"(v.y) : "l"(p));
    return v;
}

// ---------------- the single persistent kernel ----------------------------
extern __shared__ float smem[];
// lstm CTA: w2_s u64[8192] (64KB) | g_sm float[2048] (8KB) | bias_s[32]
// proj CTA: w_s float[8320] | bo_s float[80 pad] | h_s float[8192] (16B-aligned)

__global__ void __launch_bounds__(NTHR, 1)
mega_kernel(const int* __restrict__ x, const float* __restrict__ embed,
            const float* __restrict__ w_ih, const float* __restrict__ b_ih,
            const float* __restrict__ w_hh, const float* __restrict__ b_hh,
            const float* __restrict__ w_out, const float* __restrict__ b_out,
            float* __restrict__ d_out, long long out_size) {
    int tid = threadIdx.x;
    int bid = blockIdx.x;
    __shared__ int xv[BB];

    // ======== phase 0: init + embed (all CTAs cooperate) ========
    {
        // zero the h ring
        float* p = &g_ring[0][0][0][0];
        const long long n = 4LL * LL * HH * BB;
        for (long long i = (long long)bid * NTHR + tid; i < n; i += (long long)NCTA * NTHR)
            p[i] = 0.0f;
        // reset counters
        if (bid == 0 && tid < LL * 32) g_done[tid] = 0u;
        // embedding gather, k-major
        for (int t = bid; t < TT; t += NCTA) {
            if (tid < BB) xv[tid] = x[tid * TT + t];
            __syncthreads();
            int b = tid >> 2, q4 = tid & 3;   // 32 floats per thread
            const float4* src = (const float4*)(embed + (long long)xv[b] * HH + q4 * 32);
#pragma unroll
            for (int i = 0; i < 8; i++) {
                float4 v = src[i];
                int k = q4 * 32 + i * 4;
                g_xe[t][k + 0][b] = v.x;
                g_xe[t][k + 1][b] = v.y;
                g_xe[t][k + 2][b] = v.z;
                g_xe[t][k + 3][b] = v.w;
            }
            __syncthreads();
        }
    }
    // ======== one-time grid barrier (monotonic, replay-safe) ========
    __syncthreads();
    if (tid == 0) {
        __threadfence();
        u64 my = atomicAdd(&g_bar_ctr, 1ULL);
        u64 ph = my / NCTA;
        if ((my % NCTA) == (NCTA - 1)) {
            __threadfence();
            *((volatile u64*)&g_bar_rel) = ph + 1;
        } else {
            while (*((volatile u64*)&g_bar_rel) <= ph) { }
        }
        __threadfence();
    }
    __syncthreads();

    // ======== proj workers ========
    if (bid >= LSTM_CTAS) {
        int p = bid - LSTM_CTAS;                  // 0..15
        float* w_s  = smem;                       // 8320 floats
        float* bo_s = smem + HH * OUTD;           // 80 floats (padded)
        float* h_s  = smem + HH * OUTD + 80;      // 33600 B offset, 16B-aligned
        for (int i = tid; i < HH * OUTD; i += NTHR) w_s[i] = w_out[i];
        for (int i = tid; i < OUTD; i += NTHR) bo_s[i] = b_out[i];
        __syncthreads();
        u32 h_base = smem_u32(h_s);
        for (int t = p; t < TT; t += PROJ_CTAS) {
            if (tid == 0) {
                while (ld_acq(&g_done[(LL - 1) * 32]) < 16u * (t + 1)) { }
            }
            __syncthreads();
            const float4* src = (const float4*)&g_h7[t][0][0];
            for (int i = tid; i < 2048; i += NTHR)
                CP16(h_base + i * 16, (const void*)(src + i));
            CP_COMMIT_WAIT();
            __syncthreads();
            for (int idx = tid; idx < BB * OUTD; idx += NTHR) {
                int b = idx / OUTD, o = idx % OUTD;
                float acc = bo_s[o];
#pragma unroll 8
                for (int k = 0; k < HH; k++)
                    acc += h_s[k * 64 + b] * w_s[k * OUTD + o];
                d_out[((long long)b * TT + t) * OUTD + o] = acc;
            }
            __syncthreads();
        }
        return;
    }

    // ======== LSTM CTAs ========
    u64*   w2_s   = (u64*)smem;                  // 8192 u64 (64KB)
    float* g_sm   = smem + 16384;                // 2048 floats (8KB), separate buffer
    float* bias_s = smem + 16384 + 2048;         // 32 floats

    int layer = bid / CTAS_PER_LAYER;
    int sub   = bid % CTAS_PER_LAYER;
    int hc0   = sub * 8;

    // one-time weight slice -> smem (f32x2-duplicated)
    for (int idx = tid; idx < 128 * 32; idx += NTHR) {
        int k = idx >> 5, c = idx & 31;
        int col = (c >> 3) * HH + hc0 + (c & 7);
        float wi = w_ih[((long long)layer * HH + k) * GG + col];
        float wh = w_hh[((long long)layer * HH + k) * GG + col];
        w2_s[k * 32 + c]         = pack2(wi, wi);
        w2_s[(k + 128) * 32 + c] = pack2(wh, wh);
    }
    if (tid < 32) {
        int col = (tid >> 3) * HH + hc0 + (tid & 7);
        bias_s[tid] = b_ih[layer * GG + col] + b_hh[layer * GG + col];
    }
    __syncthreads();

    // GEMM mapping: team = cols [0..16)|[16..32); tb = 4-batch group; tc = 2-col group
    int team = tid >> 7;
    int q    = tid & 127;
    int tb   = q >> 3;                // 0..15
    int tc   = q & 7;                 // 0..7
    int c0   = team * 16 + 2 * tc;

    u64 biasp0 = pack2(bias_s[c0],     bias_s[c0]);
    u64 biasp1 = pack2(bias_s[c0 + 1], bias_s[c0 + 1]);

    float c_reg[2] = {0.f, 0.f};

    for (int t = 0; t < TT; t++) {
        // ---- waits ----
        if (tid == 0) {
            if (layer > 0) while (ld_acq(&g_done[(layer - 1) * 32]) < 16u * (t + 1)) { }
            if (t > 0)     while (ld_acq(&g_done[layer * 32])       < 16u * t) { }
            if (layer < LL - 1 && t >= 4)
                while (ld_acq(&g_done[(layer + 1) * 32]) < 16u * (t - 3)) { }
        }
        __syncthreads();   // S1

        // ---- GEMM straight from L2 (no smem staging) ----
        const ulonglong2* iA = (layer == 0)
            ? (const ulonglong2*)&g_xe[t][0][0]
            : (const ulonglong2*)&g_ring[t & 3][layer - 1][0][0];
        const ulonglong2* hA = (const ulonglong2*)&g_ring[(t - 1) & 3][layer][0][0];

        u64 acc00 = biasp0, acc10 = biasp0, acc01 = biasp1, acc11 = biasp1;

#pragma unroll 16
        for (int k = 0; k < 128; k++) {
            ulonglong2 av = ldcg2(iA + k * 16 + tb);
            ulonglong2 wv = *(const ulonglong2*)&w2_s[k * 32 + c0];
            FMA2(acc00, av.x, wv.x); FMA2(acc10, av.y, wv.x);
            FMA2(acc01, av.x, wv.y); FMA2(acc11, av.y, wv.y);
        }
#pragma unroll 16
        for (int k = 0; k < 128; k++) {
            ulonglong2 av = ldcg2(hA + k * 16 + tb);
            ulonglong2 wv = *(const ulonglong2*)&w2_s[(k + 128) * 32 + c0];
            FMA2(acc00, av.x, wv.x); FMA2(acc10, av.y, wv.x);
            FMA2(acc01, av.x, wv.y); FMA2(acc11, av.y, wv.y);
        }

        // ---- gate exchange into dedicated buffer ----
        {
            u64* dst0 = (u64*)(g_sm + c0 * 64 + 4 * tb);
            u64* dst1 = (u64*)(g_sm + (c0 + 1) * 64 + 4 * tb);
            dst0[0] = acc00; dst0[1] = acc10;
            dst1[0] = acc01; dst1[1] = acc11;
        }
        __syncthreads();   // S2: gates visible (also: all GEMM reads done)

        // ---- fused elementwise: 2 cells/thread ----
#pragma unroll
        for (int ii = 0; ii < 2; ii++) {
            int cell = tid + ii * 256;           // 0..511
            int j = cell >> 6, b = cell & 63;
            float gi = g_sm[(0  + j) * 64 + b];
            float gf = g_sm[(8  + j) * 64 + b];
            float gg = g_sm[(16 + j) * 64 + b];
            float go = g_sm[(24 + j) * 64 + b];
            float iv = sigf(gi);
            float fv = sigf(gf);
            float gv = tanhf_(gg);
            float ov = sigf(go);
            float cp = (t == 0) ? 0.0f : c_reg[ii];
            float cn = fv * cp + iv * gv;
            float hv = ov * tanhf_(cn);
            c_reg[ii] = cn;
            g_ring[t & 3][layer][hc0 + j][b] = hv;
            if (layer == LL - 1) g_h7[t][hc0 + j][b] = hv;
            if (t == TT - 1 && out_size >= TOTALOUT) {
                long long base = OUTBASE + ((long long)layer * BB + b) * HH + hc0 + j;
                d_out[base] = hv;
                d_out[base + STATESZ] = cn;
            }
        }
        __syncthreads();   // S3: all stores issued before signal
        if (tid == 0) red_rel(&g_done[layer * 32]);
    }
}

// ---------------- launch ---------------------------------------------------
extern "C" void kernel_launch(void* const* d_in, const int* in_sizes, int n_in,
                              void* d_out, int out_size) {
    const int*   x     = (const int*)d_in[0];
    const float* embed = (const float*)d_in[1];
    const float* w_ih  = (const float*)d_in[2];
    const float* b_ih  = (const float*)d_in[3];
    const float* w_hh  = (const float*)d_in[4];
    const float* b_hh  = (const float*)d_in[5];
    const float* w_out = (const float*)d_in[6];
    const float* b_out = (const float*)d_in[7];
    float* out = (float*)d_out;

    size_t smem_bytes = (16384 + 2048 + 64) * sizeof(float);   // ~72.25 KB
    cudaFuncSetAttribute(mega_kernel, cudaFuncAttributeMaxDynamicSharedMemorySize,
                         (int)smem_bytes);

    mega_kernel<<<NCTA, NTHR, smem_bytes>>>(x, embed, w_ih, b_ih, w_hh, b_hh,
                                            w_out, b_out, out, (long long)out_size);
}

// round 16
// speedup vs baseline: 1.1558x; 1.1558x over previous
#include <cuda_runtime.h>

#define BB 64
#define TT 512
#define HH 128
#define LL 8
#define OUTD 65
#define GG 512
#define CTAS_PER_LAYER 16
#define LSTM_CTAS (LL * CTAS_PER_LAYER)   // 128
#define PROJ_CTAS 16
#define NCTA (LSTM_CTAS + PROJ_CTAS)      // 144
#define NTHR 256

#define OUTBASE ((long long)BB * TT * OUTD)
#define STATESZ ((long long)LL * BB * HH)
#define TOTALOUT (OUTBASE + 2 * STATESZ)

typedef unsigned long long u64;
typedef unsigned int u32;

// ---------------- device scratch ------------------------------------------
__device__ float g_ring[4][LL][HH][BB];   // 4-deep h ring, k-major
__device__ float g_xe[TT][HH][BB];        // embedded input, k-major
__device__ float g_h7[TT][HH][BB];        // layer-7 h stream
__device__ u32 g_done[LL * 32];           // per-layer counters (64B apart)
__device__ u64 g_bar_ctr = 0;             // one-time grid barrier (monotonic)
__device__ u64 g_bar_rel = 0;

// ---------------- helpers -------------------------------------------------
__device__ __forceinline__ float sigf(float x) { return 1.0f / (1.0f + __expf(-x)); }
__device__ __forceinline__ float tanhf_(float x) { return 2.0f / (1.0f + __expf(-2.0f * x)) - 1.0f; }
__device__ __forceinline__ u64 pack2(float x, float y) {
    u64 r; asm("mov.b64 %0, {%1,%2};" : "=l"(r) : "f"(x), "f"(y)); return r;
}
#define FMA2(d, a, b) \
    asm("fma.rn.f32x2 %0, %1, %2, %0;" : "+l"(d) : "l"(a), "l"(b))

__device__ __forceinline__ u32 ld_acq(const u32* p) {
    u32 v; asm volatile("ld.acquire.gpu.global.u32 %0, [%1];" : "=r"(v) : "l"(p)); return v;
}
__device__ __forceinline__ void red_rel(u32* p) {
    asm volatile("red.release.gpu.global.add.u32 [%0], %1;" :: "l"(p), "r"(1u) : "memory");
}
__device__ __forceinline__ u32 smem_u32(const void* p) {
    return (u32)__cvta_generic_to_shared(p);
}
#define CP16(s, g) asm volatile("cp.async.cg.shared.global [%0], [%1], 16;" :: "r"(s), "l"(g))
#define CP_COMMIT_WAIT() do { \
    asm volatile("cp.async.commit_group;"); \
    asm volatile("cp.async.wait_group 0;" ::: "memory"); } while (0)

// ---------------- the single persistent kernel ----------------------------
extern __shared__ float smem[];
// lstm CTA: w2_s u64[8192] (64KB) | a_s float[16384] (64KB) | g_sm float[2048] (8KB) | bias_s[32]
// proj CTA: w_s float[8320] | bo_s float[80 pad] | h_s float[8192] (16B-aligned)

__global__ void __launch_bounds__(NTHR, 1)
mega_kernel(const int* __restrict__ x, const float* __restrict__ embed,
            const float* __restrict__ w_ih, const float* __restrict__ b_ih,
            const float* __restrict__ w_hh, const float* __restrict__ b_hh,
            const float* __restrict__ w_out, const float* __restrict__ b_out,
            float* __restrict__ d_out, long long out_size) {
    int tid = threadIdx.x;
    int bid = blockIdx.x;
    __shared__ int xv[BB];

    // ======== phase 0: init + embed (all CTAs cooperate) ========
    {
        float* p = &g_ring[0][0][0][0];
        const long long n = 4LL * LL * HH * BB;
        for (long long i = (long long)bid * NTHR + tid; i < n; i += (long long)NCTA * NTHR)
            p[i] = 0.0f;
        if (bid == 0 && tid < LL * 32) g_done[tid] = 0u;
        for (int t = bid; t < TT; t += NCTA) {
            if (tid < BB) xv[tid] = x[tid * TT + t];
            __syncthreads();
            int b = tid >> 2, q4 = tid & 3;
            const float4* src = (const float4*)(embed + (long long)xv[b] * HH + q4 * 32);
#pragma unroll
            for (int i = 0; i < 8; i++) {
                float4 v = src[i];
                int k = q4 * 32 + i * 4;
                g_xe[t][k + 0][b] = v.x;
                g_xe[t][k + 1][b] = v.y;
                g_xe[t][k + 2][b] = v.z;
                g_xe[t][k + 3][b] = v.w;
            }
            __syncthreads();
        }
    }
    // ======== one-time grid barrier (monotonic, replay-safe) ========
    __syncthreads();
    if (tid == 0) {
        __threadfence();
        u64 my = atomicAdd(&g_bar_ctr, 1ULL);
        u64 ph = my / NCTA;
        if ((my % NCTA) == (NCTA - 1)) {
            __threadfence();
            *((volatile u64*)&g_bar_rel) = ph + 1;
        } else {
            while (*((volatile u64*)&g_bar_rel) <= ph) { }
        }
        __threadfence();
    }
    __syncthreads();

    // ======== proj workers ========
    if (bid >= LSTM_CTAS) {
        int p = bid - LSTM_CTAS;
        float* w_s  = smem;
        float* bo_s = smem + HH * OUTD;
        float* h_s  = smem + HH * OUTD + 80;      // 16B-aligned
        for (int i = tid; i < HH * OUTD; i += NTHR) w_s[i] = w_out[i];
        for (int i = tid; i < OUTD; i += NTHR) bo_s[i] = b_out[i];
        __syncthreads();
        u32 h_base = smem_u32(h_s);
        for (int t = p; t < TT; t += PROJ_CTAS) {
            if (tid == 0) {
                while (ld_acq(&g_done[(LL - 1) * 32]) < 16u * (t + 1)) { }
            }
            __syncthreads();
            const float4* src = (const float4*)&g_h7[t][0][0];
            for (int i = tid; i < 2048; i += NTHR)
                CP16(h_base + i * 16, (const void*)(src + i));
            CP_COMMIT_WAIT();
            __syncthreads();
            for (int idx = tid; idx < BB * OUTD; idx += NTHR) {
                int b = idx / OUTD, o = idx % OUTD;
                float acc = bo_s[o];
#pragma unroll 8
                for (int k = 0; k < HH; k++)
                    acc += h_s[k * 64 + b] * w_s[k * OUTD + o];
                d_out[((long long)b * TT + t) * OUTD + o] = acc;
            }
            __syncthreads();
        }
        return;
    }

    // ======== LSTM CTAs ========
    u64*   w2_s   = (u64*)smem;                  // 8192 u64 (64KB)
    float* a_s    = smem + 16384;                // 16384 floats (64KB)
    float* g_sm   = smem + 16384 + 16384;        // 2048 floats (8KB)
    float* bias_s = smem + 16384 + 16384 + 2048; // 32 floats

    int layer = bid / CTAS_PER_LAYER;
    int sub   = bid % CTAS_PER_LAYER;
    int hc0   = sub * 8;

    // one-time weight slice -> smem (f32x2-duplicated)
    for (int idx = tid; idx < 128 * 32; idx += NTHR) {
        int k = idx >> 5, c = idx & 31;
        int col = (c >> 3) * HH + hc0 + (c & 7);
        float wi = w_ih[((long long)layer * HH + k) * GG + col];
        float wh = w_hh[((long long)layer * HH + k) * GG + col];
        w2_s[k * 32 + c]         = pack2(wi, wi);
        w2_s[(k + 128) * 32 + c] = pack2(wh, wh);
    }
    if (tid < 32) {
        int col = (tid >> 3) * HH + hc0 + (tid & 7);
        bias_s[tid] = b_ih[layer * GG + col] + b_hh[layer * GG + col];
    }
    __syncthreads();

    // GEMM mapping: team = cols [0..16)|[16..32); tb = 4-batch group; tc = 2-col group
    int team = tid >> 7;
    int q    = tid & 127;
    int tb   = q >> 3;                // 0..15
    int tc   = q & 7;                 // 0..7
    int c0   = team * 16 + 2 * tc;

    u64 biasp0 = pack2(bias_s[c0],     bias_s[c0]);
    u64 biasp1 = pack2(bias_s[c0 + 1], bias_s[c0 + 1]);

    float c_reg[2] = {0.f, 0.f};

    const ulonglong2* aU = (const ulonglong2*)a_s;
    u32 a_base = smem_u32(a_s);

    for (int t = 0; t < TT; t++) {
        // ---- slack wait: own-layer peers done with step t-1 ----
        if (tid == 0 && t > 0) {
            while (ld_acq(&g_done[layer * 32]) < 16u * t) { }
        }
        __syncthreads();

        // ---- stage own h(t-1) into a_s upper half, GEMM-hh (no producer needed) ----
        const float4* h4 = (const float4*)&g_ring[(t - 1) & 3][layer][0][0];
        for (int i = tid; i < 2048; i += NTHR)
            CP16(a_base + 32768 + i * 16, (const void*)(h4 + i));
        CP_COMMIT_WAIT();
        __syncthreads();

        u64 acc00 = biasp0, acc10 = biasp0, acc01 = biasp1, acc11 = biasp1;
#pragma unroll 16
        for (int k = 128; k < 256; k++) {
            ulonglong2 av = aU[k * 16 + tb];
            ulonglong2 wv = *(const ulonglong2*)&w2_s[k * 32 + c0];
            FMA2(acc00, av.x, wv.x); FMA2(acc10, av.y, wv.x);
            FMA2(acc01, av.x, wv.y); FMA2(acc11, av.y, wv.y);
        }

        // ---- now wait for producer (overlapped with the hh work above) ----
        if (tid == 0) {
            if (layer > 0) while (ld_acq(&g_done[(layer - 1) * 32]) < 16u * (t + 1)) { }
            if (layer < LL - 1 && t >= 4)
                while (ld_acq(&g_done[(layer + 1) * 32]) < 16u * (t - 3)) { }
        }
        __syncthreads();

        // ---- stage input(t) into a_s lower half, GEMM-ih ----
        const float4* i4 = (layer == 0)
            ? (const float4*)&g_xe[t][0][0]
            : (const float4*)&g_ring[t & 3][layer - 1][0][0];
        for (int i = tid; i < 2048; i += NTHR)
            CP16(a_base + i * 16, (const void*)(i4 + i));
        CP_COMMIT_WAIT();
        __syncthreads();

#pragma unroll 16
        for (int k = 0; k < 128; k++) {
            ulonglong2 av = aU[k * 16 + tb];
            ulonglong2 wv = *(const ulonglong2*)&w2_s[k * 32 + c0];
            FMA2(acc00, av.x, wv.x); FMA2(acc10, av.y, wv.x);
            FMA2(acc01, av.x, wv.y); FMA2(acc11, av.y, wv.y);
        }

        // ---- gate exchange into dedicated buffer ----
        {
            u64* dst0 = (u64*)(g_sm + c0 * 64 + 4 * tb);
            u64* dst1 = (u64*)(g_sm + (c0 + 1) * 64 + 4 * tb);
            dst0[0] = acc00; dst0[1] = acc10;
            dst1[0] = acc01; dst1[1] = acc11;
        }
        __syncthreads();   // gates visible

        // ---- fused elementwise: 2 cells/thread ----
#pragma unroll
        for (int ii = 0; ii < 2; ii++) {
            int cell = tid + ii * 256;
            int j = cell >> 6, b = cell & 63;
            float gi = g_sm[(0  + j) * 64 + b];
            float gf = g_sm[(8  + j) * 64 + b];
            float gg = g_sm[(16 + j) * 64 + b];
            float go = g_sm[(24 + j) * 64 + b];
            float iv = sigf(gi);
            float fv = sigf(gf);
            float gv = tanhf_(gg);
            float ov = sigf(go);
            float cp = (t == 0) ? 0.0f : c_reg[ii];
            float cn = fv * cp + iv * gv;
            float hv = ov * tanhf_(cn);
            c_reg[ii] = cn;
            g_ring[t & 3][layer][hc0 + j][b] = hv;
            if (layer == LL - 1) g_h7[t][hc0 + j][b] = hv;
            if (t == TT - 1 && out_size >= TOTALOUT) {
                long long base = OUTBASE + ((long long)layer * BB + b) * HH + hc0 + j;
                d_out[base] = hv;
                d_out[base + STATESZ] = cn;
            }
        }
        __syncthreads();   // all stores issued before signal
        if (tid == 0) red_rel(&g_done[layer * 32]);
    }
}

// ---------------- launch ---------------------------------------------------
extern "C" void kernel_launch(void* const* d_in, const int* in_sizes, int n_in,
                              void* d_out, int out_size) {
    const int*   x     = (const int*)d_in[0];
    const float* embed = (const float*)d_in[1];
    const float* w_ih  = (const float*)d_in[2];
    const float* b_ih  = (const float*)d_in[3];
    const float* w_hh  = (const float*)d_in[4];
    const float* b_hh  = (const float*)d_in[5];
    const float* w_out = (const float*)d_in[6];
    const float* b_out = (const float*)d_in[7];
    float* out = (float*)d_out;

    size_t smem_bytes = (16384 + 16384 + 2048 + 64) * sizeof(float);   // ~136.25 KB
    cudaFuncSetAttribute(mega_kernel, cudaFuncAttributeMaxDynamicSharedMemorySize,
                         (int)smem_bytes);

    mega_kernel<<<NCTA, NTHR, smem_bytes>>>(x, embed, w_ih, b_ih, w_hh, b_hh,
                                            w_out, b_out, out, (long long)out_size);
}